// round 3
// baseline (speedup 1.0000x reference)
#include <cuda_runtime.h>

#define ADAM_B1 0.9f
#define ADAM_B2 0.999f
#define ADAM_LR 0.02f

// ---------------- packed f32x2 helpers ----------------
struct F2 { unsigned long long v; };

__device__ __forceinline__ F2 pk(float lo, float hi) {
    F2 r; asm("mov.b64 %0, {%1, %2};" : "=l"(r.v) : "f"(lo), "f"(hi)); return r;
}
__device__ __forceinline__ void upk(F2 a, float& lo, float& hi) {
    asm("mov.b64 {%0, %1}, %2;" : "=f"(lo), "=f"(hi) : "l"(a.v));
}
__device__ __forceinline__ F2 bc(float s) { return pk(s, s); }
__device__ __forceinline__ F2 fadd2(F2 a, F2 b) {
    F2 r; asm("add.rn.f32x2 %0, %1, %2;" : "=l"(r.v) : "l"(a.v), "l"(b.v)); return r;
}
__device__ __forceinline__ F2 fmul2(F2 a, F2 b) {
    F2 r; asm("mul.rn.f32x2 %0, %1, %2;" : "=l"(r.v) : "l"(a.v), "l"(b.v)); return r;
}
__device__ __forceinline__ F2 ffma2(F2 a, F2 b, F2 c) {
    F2 r; asm("fma.rn.f32x2 %0, %1, %2, %3;" : "=l"(r.v) : "l"(a.v), "l"(b.v), "l"(c.v)); return r;
}

__device__ __forceinline__ float rcp_a(float x) {
    float r; asm("rcp.approx.f32 %0, %1;" : "=f"(r) : "f"(x)); return r;
}
__device__ __forceinline__ float rsq_a(float x) {
    float r; asm("rsqrt.approx.f32 %0, %1;" : "=f"(r) : "f"(x)); return r;
}
__device__ __forceinline__ float ex2_a(float x) {
    float r; asm("ex2.approx.f32 %0, %1;" : "=f"(r) : "f"(x)); return r;
}
__device__ __forceinline__ F2 frcp2(F2 a) {
    float lo, hi; upk(a, lo, hi); return pk(rcp_a(lo), rcp_a(hi));
}
__device__ __forceinline__ F2 frsq2(F2 a) {
    float lo, hi; upk(a, lo, hi); return pk(rsq_a(lo), rsq_a(hi));
}
__device__ __forceinline__ F2 fexp2(F2 a, F2 LOG2E) {
    F2 t = fmul2(a, LOG2E);
    float lo, hi; upk(t, lo, hi);
    return pk(ex2_a(lo), ex2_a(hi));
}

// ---------------- Adam bias-correction table ----------------
// E_t = (1-b1^t)^2 / (1-b2^t)  so that  mh/sqrt(vh) = m * rsqrt(v * E_t)
__device__ float g_E[512];

__global__ void init_E() {
    if (threadIdx.x == 0 && blockIdx.x == 0) {
        float b1t = 1.0f, b2t = 1.0f;
        for (int t = 0; t < 512; t++) {
            b1t *= ADAM_B1; b2t *= ADAM_B2;
            float d1 = 1.0f - b1t, d2 = 1.0f - b2t;
            g_E[t] = d1 * d1 / d2;
        }
    }
}

// ---------------- main kernel: 2 pixels per thread, packed ----------------
__global__ __launch_bounds__(128)
void pe_kernel(const float* __restrict__ X,     // (B,5,5)
               const float* __restrict__ Yg,    // (B,5)
               const float* __restrict__ ch0g,  // (B,1,3)
               const float* __restrict__ pf,    // (14,)
               const float* __restrict__ xag,   // (3,)
               const float* __restrict__ Sag,   // (3,3)
               const float* __restrict__ Seg,   // (5,5)
               const int*   __restrict__ nitp,
               float* __restrict__ out,         // (B,9)
               int B)
{
    int tIdx = blockIdx.x * blockDim.x + threadIdx.x;
    int pA = 2 * tIdx;
    if (pA >= B) return;
    int pB = min(pA + 1, B - 1);

    const float L[5] = {-0.275f, 0.025f, 0.5f, 0.70f, 1.15f};

    // ---- uniform (broadcast) parameters ----
    float p0=pf[0], p1=pf[1], p2=pf[2], p3=pf[3], p4=pf[4], p5=pf[5], p6=pf[6],
          p7=pf[7], p8=pf[8], p9=pf[9], p10=pf[10], p11=pf[11], p12=pf[12], p13=pf[13];

    float AphS[5], AcdS[5], BbsS[5];
    #pragma unroll
    for (int l = 0; l < 5; l++) {
        AphS[l] = p0 * 0.05f * (1.0f + p1 * 0.1f * L[l] + p2 * 0.01f);
        AcdS[l] = p5 * 0.1f * expf(-p6 * 1.7f * L[l]);
        BbsS[l] = p3 * 0.001f * (1.0f + p4 * 0.05f * L[l]);
    }
    const float cna = p12 * 0.005f;
    const float cnb = p13 * 0.005f;
    const float c7s = p7 * 0.089f;
    const float c8s = p8 * 0.1245f;

    // symmetrized matrices (scalar registers; uniform across warp)
    float Se[5][5];
    #pragma unroll
    for (int i = 0; i < 5; i++)
        #pragma unroll
        for (int j = 0; j < 5; j++)
            Se[i][j] = 0.5f * (Seg[i*5 + j] + Seg[j*5 + i]);
    float SaS[3][3];
    #pragma unroll
    for (int i = 0; i < 3; i++)
        #pragma unroll
        for (int j = 0; j < 3; j++)
            SaS[i][j] = 0.5f * (Sag[i*3 + j] + Sag[j*3 + i]);
    float xa0 = xag[0], xa1 = xag[1], xa2 = xag[2];
    // fold prior offset: g_prior = Sa*ch - Sa*xa
    float bp0 = -(SaS[0][0]*xa0 + SaS[0][1]*xa1 + SaS[0][2]*xa2);
    float bp1 = -(SaS[1][0]*xa0 + SaS[1][1]*xa1 + SaS[1][2]*xa2);
    float bp2 = -(SaS[2][0]*xa0 + SaS[2][1]*xa1 + SaS[2][2]*xa2);

    // ---- packed constants ----
    const F2 APH[5] = { bc(AphS[0]), bc(AphS[1]), bc(AphS[2]), bc(AphS[3]), bc(AphS[4]) };
    const F2 ACD[5] = { bc(AcdS[0]), bc(AcdS[1]), bc(AcdS[2]), bc(AcdS[3]), bc(AcdS[4]) };
    const F2 BBS[5] = { bc(BbsS[0]), bc(BbsS[1]), bc(BbsS[2]), bc(BbsS[3]), bc(BbsS[4]) };
    const F2 CNA = bc(cna), CNB = bc(cnb);
    const F2 C7 = bc(c7s), C8 = bc(c8s), C82 = bc(2.0f * c8s);
    const F2 C0045 = bc(0.0045f), C0012 = bc(0.0012f);
    const F2 NEG1 = bc(-1.0f), ONE = bc(1.0f);
    const F2 LOG2E = bc(1.4426950408889634f);
    const F2 CB1 = bc(ADAM_B1), C1MB1 = bc(1.0f - ADAM_B1);
    const F2 CB2 = bc(ADAM_B2), C1MB2 = bc(1.0f - ADAM_B2);
    const F2 NEGLR = bc(-ADAM_LR), TINY = bc(1e-30f);
    const F2 SA00 = bc(SaS[0][0]), SA01 = bc(SaS[0][1]), SA02 = bc(SaS[0][2]);
    const F2 SA10 = bc(SaS[1][0]), SA11 = bc(SaS[1][1]), SA12 = bc(SaS[1][2]);
    const F2 SA20 = bc(SaS[2][0]), SA21 = bc(SaS[2][1]), SA22 = bc(SaS[2][2]);
    const F2 BP0 = bc(bp0), BP1 = bc(bp1), BP2 = bc(bp2);

    // ---- per-pixel packed constants ----
    F2 FE[5], Yp[5];
    #pragma unroll
    for (int l = 0; l < 5; l++) {
        float eA0 = X[pA*25 + l*5 + 0], eA1 = X[pA*25 + l*5 + 1];
        float eB0 = X[pB*25 + l*5 + 0], eB1 = X[pB*25 + l*5 + 1];
        FE[l] = pk(__fdividef(eA0 + 0.5f*eA1, eA0 + eA1),
                   __fdividef(eB0 + 0.5f*eB1, eB0 + eB1));
        Yp[l] = pk(Yg[pA*5 + l], Yg[pB*5 + l]);
    }

    F2 ch[3], m[3], v[3];
    #pragma unroll
    for (int k = 0; k < 3; k++) {
        ch[k] = pk(ch0g[pA*3 + k], ch0g[pB*3 + k]);
        m[k] = bc(0.0f); v[k] = bc(0.0f);
    }

    // ---- iteration count ----
    int iters = 50;
    if (nitp) {
        int it = *nitp;
        if (it >= 1 && it <= 100000000) iters = it;
        else {
            float f = __int_as_float(it);
            if (f >= 1.0f && f <= 1e8f) iters = (int)f;
        }
    }

    // ---- Adam loop ----
    for (int t = 0; t < iters; t++) {
        F2 chla = fexp2(ch[0], LOG2E);
        F2 nap  = fexp2(ch[1], LOG2E);
        F2 cdom = fexp2(ch[2], LOG2E);

        F2 da1  = fmul2(CNA, nap);
        F2 dbb1 = fmul2(CNB, nap);

        F2 u[5], iv[5];
        float rA[5], rB[5];
        #pragma unroll
        for (int l = 0; l < 5; l++) {
            F2 da0  = fmul2(APH[l], chla);
            F2 da2  = fmul2(ACD[l], cdom);
            F2 dbb0 = fmul2(BBS[l], chla);
            F2 a  = fadd2(fadd2(da0, da2), fadd2(da1, C0045));
            F2 bb = fadd2(dbb0, fadd2(dbb1, C0012));
            F2 ivv = frcp2(fadd2(a, bb));
            F2 uv  = fmul2(bb, ivv);
            F2 rrs = fmul2(fmul2(ffma2(C8, uv, C7), uv), FE[l]);
            F2 rr  = ffma2(Yp[l], NEG1, rrs);     // rrs - Y
            upk(rr, rA[l], rB[l]);
            u[l] = uv; iv[l] = ivv;
        }

        // prior gradient (packed): Sa*ch + (-Sa*xa)
        F2 g0 = ffma2(SA00, ch[0], ffma2(SA01, ch[1], ffma2(SA02, ch[2], BP0)));
        F2 g1 = ffma2(SA10, ch[0], ffma2(SA11, ch[1], ffma2(SA12, ch[2], BP1)));
        F2 g2 = ffma2(SA20, ch[0], ffma2(SA21, ch[1], ffma2(SA22, ch[2], BP2)));

        #pragma unroll
        for (int l = 0; l < 5; l++) {
            // Se*r contraction in scalar (Se uniform -> no packed const cost)
            float wA = fmaf(Se[l][0], rA[0], fmaf(Se[l][1], rA[1],
                       fmaf(Se[l][2], rA[2], fmaf(Se[l][3], rA[3], Se[l][4]*rA[4]))));
            float wB = fmaf(Se[l][0], rB[0], fmaf(Se[l][1], rB[1],
                       fmaf(Se[l][2], rB[2], fmaf(Se[l][3], rB[3], Se[l][4]*rB[4]))));
            F2 w  = pk(wA, wB);
            F2 dg = fmul2(ffma2(C82, u[l], C7), FE[l]);
            F2 q  = fmul2(fmul2(w, dg), iv[l]);

            F2 da0  = fmul2(APH[l], chla);
            F2 dbb0 = fmul2(BBS[l], chla);
            F2 da2  = fmul2(ACD[l], cdom);
            F2 om   = ffma2(u[l], NEG1, ONE);

            F2 x0 = ffma2(fmul2(u[l], da0), NEG1, fmul2(om, dbb0));
            g0 = ffma2(q, x0, g0);
            F2 x1 = ffma2(fmul2(u[l], da1), NEG1, fmul2(om, dbb1));
            g1 = ffma2(q, x1, g1);
            F2 qun = fmul2(fmul2(q, u[l]), NEG1);
            g2 = ffma2(qun, da2, g2);
        }

        // Adam with exact bias correction folded into E_t
        F2 E2 = bc((t < 512) ? g_E[t] : 1.0f);
        F2 g[3] = { g0, g1, g2 };
        #pragma unroll
        for (int k = 0; k < 3; k++) {
            m[k] = ffma2(g[k], C1MB1, fmul2(m[k], CB1));
            v[k] = ffma2(fmul2(g[k], g[k]), C1MB2, fmul2(v[k], CB2));
            F2 st = frsq2(ffma2(v[k], E2, TINY));
            ch[k] = ffma2(fmul2(m[k], st), NEGLR, ch[k]);
        }
    }

    // ---- outputs: [ch0, kd(5), bbp(3)] per pixel ----
    float kfac = p9 * 0.9f + p10 * 0.1f;
    float chL[3], chH[3];
    #pragma unroll
    for (int k = 0; k < 3; k++) upk(ch[k], chL[k], chH[k]);

    #pragma unroll
    for (int s = 0; s < 2; s++) {
        int b = s ? pB : pA;
        const float* chp = s ? chH : chL;
        float chla = __expf(chp[0]);
        float nap  = __expf(chp[1]);
        float cdom = __expf(chp[2]);

        out[b*9 + 0] = chp[0];
        #pragma unroll
        for (int l = 0; l < 5; l++) {
            float a  = 0.0045f + AphS[l]*chla + AcdS[l]*cdom + cna*nap;
            float bb = 0.0012f + BbsS[l]*chla + cnb*nap;
            float x3 = X[b*25 + l*5 + 3];
            float mu = 0.5f + 0.5f * rcp_a(1.0f + __expf(-x3));
            out[b*9 + 1 + l] = (a + bb) * rcp_a(mu) * kfac;
        }
        const float L3[3] = {0.025f, 0.5f, 1.15f};
        #pragma unroll
        for (int j = 0; j < 3; j++) {
            out[b*9 + 6 + j] = p11 * (p3 * 0.001f * chla * (1.0f + p4 * 0.05f * L3[j]) + cnb * nap);
        }
    }
}

extern "C" void kernel_launch(void* const* d_in, const int* in_sizes, int n_in,
                              void* d_out, int out_size) {
    const float* X    = (const float*)d_in[0];
    const float* Y    = (const float*)d_in[1];
    const float* ch0  = (const float*)d_in[2];
    const float* pf   = (const float*)d_in[3];
    const float* xa   = (const float*)d_in[4];
    const float* Sa   = (const float*)d_in[5];
    const float* Se   = (const float*)d_in[6];
    const int*   nit  = (n_in >= 8) ? (const int*)d_in[7] : nullptr;
    float* out = (float*)d_out;

    int B = in_sizes[1] / 5;   // Y is (B,5)
    int nThreads = (B + 1) / 2;

    init_E<<<1, 32>>>();

    const int TPB = 128;
    int blocks = (nThreads + TPB - 1) / TPB;
    pe_kernel<<<blocks, TPB>>>(X, Y, ch0, pf, xa, Sa, Se, nit, out, B);
}

// round 4
// speedup vs baseline: 1.2351x; 1.2351x over previous
#include <cuda_runtime.h>

#define ADAM_B1 0.9f
#define ADAM_B2 0.999f
#define ADAM_LR 0.02f

// ---------------- packed f32x2 helpers ----------------
struct F2 { unsigned long long v; };

__device__ __forceinline__ F2 pk(float lo, float hi) {
    F2 r; asm("mov.b64 %0, {%1, %2};" : "=l"(r.v) : "f"(lo), "f"(hi)); return r;
}
__device__ __forceinline__ void upk(F2 a, float& lo, float& hi) {
    asm("mov.b64 {%0, %1}, %2;" : "=f"(lo), "=f"(hi) : "l"(a.v));
}
__device__ __forceinline__ F2 bc(float s) { return pk(s, s); }
__device__ __forceinline__ F2 fadd2(F2 a, F2 b) {
    F2 r; asm("add.rn.f32x2 %0, %1, %2;" : "=l"(r.v) : "l"(a.v), "l"(b.v)); return r;
}
__device__ __forceinline__ F2 fmul2(F2 a, F2 b) {
    F2 r; asm("mul.rn.f32x2 %0, %1, %2;" : "=l"(r.v) : "l"(a.v), "l"(b.v)); return r;
}
__device__ __forceinline__ F2 ffma2(F2 a, F2 b, F2 c) {
    F2 r; asm("fma.rn.f32x2 %0, %1, %2, %3;" : "=l"(r.v) : "l"(a.v), "l"(b.v), "l"(c.v)); return r;
}

__device__ __forceinline__ float rcp_a(float x) {
    float r; asm("rcp.approx.f32 %0, %1;" : "=f"(r) : "f"(x)); return r;
}
__device__ __forceinline__ float rsq_a(float x) {
    float r; asm("rsqrt.approx.f32 %0, %1;" : "=f"(r) : "f"(x)); return r;
}
__device__ __forceinline__ float ex2_a(float x) {
    float r; asm("ex2.approx.f32 %0, %1;" : "=f"(r) : "f"(x)); return r;
}
__device__ __forceinline__ F2 frcp2(F2 a) {
    float lo, hi; upk(a, lo, hi); return pk(rcp_a(lo), rcp_a(hi));
}
__device__ __forceinline__ F2 frsq2(F2 a) {
    float lo, hi; upk(a, lo, hi); return pk(rsq_a(lo), rsq_a(hi));
}
__device__ __forceinline__ F2 fexp2(F2 a, F2 LOG2E) {
    F2 t = fmul2(a, LOG2E);
    float lo, hi; upk(t, lo, hi);
    return pk(ex2_a(lo), ex2_a(hi));
}

// ---------------- main kernel: 2 pixels per thread, packed ----------------
__global__ __launch_bounds__(128, 4)
void pe_kernel(const float* __restrict__ X,     // (B,5,5)
               const float* __restrict__ Yg,    // (B,5)
               const float* __restrict__ ch0g,  // (B,1,3)
               const float* __restrict__ pf,    // (14,)
               const float* __restrict__ xag,   // (3,)
               const float* __restrict__ Sag,   // (3,3)
               const float* __restrict__ Seg,   // (5,5)
               const int*   __restrict__ nitp,
               float* __restrict__ out,         // (B,9)
               int B)
{
    int tIdx = blockIdx.x * blockDim.x + threadIdx.x;
    int pA = 2 * tIdx;
    if (pA >= B) return;
    int pB = min(pA + 1, B - 1);

    const float L[5] = {-0.275f, 0.025f, 0.5f, 0.70f, 1.15f};

    // ---- uniform (broadcast) parameters ----
    float p0=pf[0], p1=pf[1], p2=pf[2], p3=pf[3], p4=pf[4], p5=pf[5], p6=pf[6],
          p7=pf[7], p8=pf[8], p9=pf[9], p10=pf[10], p11=pf[11], p12=pf[12], p13=pf[13];

    float AphS[5], AcdS[5], BbsS[5];
    #pragma unroll
    for (int l = 0; l < 5; l++) {
        AphS[l] = p0 * 0.05f * (1.0f + p1 * 0.1f * L[l] + p2 * 0.01f);
        AcdS[l] = p5 * 0.1f * expf(-p6 * 1.7f * L[l]);
        BbsS[l] = p3 * 0.001f * (1.0f + p4 * 0.05f * L[l]);
    }
    const float cna = p12 * 0.005f;
    const float cnb = p13 * 0.005f;
    const float c7s = p7 * 0.089f;
    const float c8s = p8 * 0.1245f;

    // symmetrized matrices (scalar registers; uniform across warp)
    float Se[5][5];
    #pragma unroll
    for (int i = 0; i < 5; i++)
        #pragma unroll
        for (int j = 0; j < 5; j++)
            Se[i][j] = 0.5f * (Seg[i*5 + j] + Seg[j*5 + i]);
    float SaS[3][3];
    #pragma unroll
    for (int i = 0; i < 3; i++)
        #pragma unroll
        for (int j = 0; j < 3; j++)
            SaS[i][j] = 0.5f * (Sag[i*3 + j] + Sag[j*3 + i]);
    float xa0 = xag[0], xa1 = xag[1], xa2 = xag[2];
    // fold prior offset: g_prior = Sa*ch - Sa*xa  (scalar)
    float bp0 = -(SaS[0][0]*xa0 + SaS[0][1]*xa1 + SaS[0][2]*xa2);
    float bp1 = -(SaS[1][0]*xa0 + SaS[1][1]*xa1 + SaS[1][2]*xa2);
    float bp2 = -(SaS[2][0]*xa0 + SaS[2][1]*xa1 + SaS[2][2]*xa2);

    // ---- packed per-wavelength constants (broadcast) ----
    const F2 APH[5] = { bc(AphS[0]), bc(AphS[1]), bc(AphS[2]), bc(AphS[3]), bc(AphS[4]) };
    const F2 ACD[5] = { bc(AcdS[0]), bc(AcdS[1]), bc(AcdS[2]), bc(AcdS[3]), bc(AcdS[4]) };
    const F2 BBS[5] = { bc(BbsS[0]), bc(BbsS[1]), bc(BbsS[2]), bc(BbsS[3]), bc(BbsS[4]) };
    const F2 CNA = bc(cna), CNB = bc(cnb);
    const F2 C7 = bc(c7s), C8 = bc(c8s), C82 = bc(2.0f * c8s);
    const F2 C0045 = bc(0.0045f), C0012 = bc(0.0012f);
    const F2 NEG1 = bc(-1.0f), ONE = bc(1.0f);
    const F2 LOG2E = bc(1.4426950408889634f);
    const F2 CB1 = bc(ADAM_B1), C1MB1 = bc(1.0f - ADAM_B1);
    const F2 CB2 = bc(ADAM_B2), C1MB2 = bc(1.0f - ADAM_B2);
    const F2 NEGLR = bc(-ADAM_LR), TINY = bc(1e-30f);

    // ---- per-pixel packed constants ----
    F2 FE[5], Yp[5];
    #pragma unroll
    for (int l = 0; l < 5; l++) {
        float eA0 = X[pA*25 + l*5 + 0], eA1 = X[pA*25 + l*5 + 1];
        float eB0 = X[pB*25 + l*5 + 0], eB1 = X[pB*25 + l*5 + 1];
        FE[l] = pk(__fdividef(eA0 + 0.5f*eA1, eA0 + eA1),
                   __fdividef(eB0 + 0.5f*eB1, eB0 + eB1));
        Yp[l] = pk(Yg[pA*5 + l], Yg[pB*5 + l]);
    }

    F2 ch[3], m[3], v[3];
    #pragma unroll
    for (int k = 0; k < 3; k++) {
        ch[k] = pk(ch0g[pA*3 + k], ch0g[pB*3 + k]);
        m[k] = bc(0.0f); v[k] = bc(0.0f);
    }

    // ---- iteration count ----
    int iters = 50;
    if (nitp) {
        int it = *nitp;
        if (it >= 1 && it <= 100000000) iters = it;
        else {
            float f = __int_as_float(it);
            if (f >= 1.0f && f <= 1e8f) iters = (int)f;
        }
    }

    // ---- Adam loop ----
    float b1t = 1.0f, b2t = 1.0f;
    for (int t = 0; t < iters; t++) {
        F2 chla = fexp2(ch[0], LOG2E);
        F2 nap  = fexp2(ch[1], LOG2E);
        F2 cdom = fexp2(ch[2], LOG2E);

        F2 da1  = fmul2(CNA, nap);
        F2 dbb1 = fmul2(CNB, nap);

        F2 u[5], iv[5];
        float rA[5], rB[5];
        #pragma unroll
        for (int l = 0; l < 5; l++) {
            F2 da0  = fmul2(APH[l], chla);
            F2 da2  = fmul2(ACD[l], cdom);
            F2 dbb0 = fmul2(BBS[l], chla);
            F2 a  = fadd2(fadd2(da0, da2), fadd2(da1, C0045));
            F2 bb = fadd2(dbb0, fadd2(dbb1, C0012));
            F2 ivv = frcp2(fadd2(a, bb));
            F2 uv  = fmul2(bb, ivv);
            F2 rrs = fmul2(fmul2(ffma2(C8, uv, C7), uv), FE[l]);
            F2 rr  = ffma2(Yp[l], NEG1, rrs);     // rrs - Y
            upk(rr, rA[l], rB[l]);
            u[l] = uv; iv[l] = ivv;
        }

        // prior gradient (scalar: pk/upk are register aliases, free)
        float cA0, cB0, cA1, cB1, cA2, cB2;
        upk(ch[0], cA0, cB0); upk(ch[1], cA1, cB1); upk(ch[2], cA2, cB2);
        float gA0 = fmaf(SaS[0][0], cA0, fmaf(SaS[0][1], cA1, fmaf(SaS[0][2], cA2, bp0)));
        float gB0 = fmaf(SaS[0][0], cB0, fmaf(SaS[0][1], cB1, fmaf(SaS[0][2], cB2, bp0)));
        float gA1 = fmaf(SaS[1][0], cA0, fmaf(SaS[1][1], cA1, fmaf(SaS[1][2], cA2, bp1)));
        float gB1 = fmaf(SaS[1][0], cB0, fmaf(SaS[1][1], cB1, fmaf(SaS[1][2], cB2, bp1)));
        float gA2 = fmaf(SaS[2][0], cA0, fmaf(SaS[2][1], cA1, fmaf(SaS[2][2], cA2, bp2)));
        float gB2 = fmaf(SaS[2][0], cB0, fmaf(SaS[2][1], cB1, fmaf(SaS[2][2], cB2, bp2)));
        F2 g0 = pk(gA0, gB0);
        F2 g1 = pk(gA1, gB1);
        F2 g2 = pk(gA2, gB2);

        // split accumulators: halve the serial chain over l
        F2 h0 = bc(0.0f), h1 = bc(0.0f), h2 = bc(0.0f);

        #pragma unroll
        for (int l = 0; l < 5; l++) {
            // Se*r contraction in scalar, tree form (depth 3)
            float wA = fmaf(Se[l][4], rA[4],
                       fmaf(Se[l][0], rA[0], Se[l][1]*rA[1]) +
                       fmaf(Se[l][2], rA[2], Se[l][3]*rA[3]));
            float wB = fmaf(Se[l][4], rB[4],
                       fmaf(Se[l][0], rB[0], Se[l][1]*rB[1]) +
                       fmaf(Se[l][2], rB[2], Se[l][3]*rB[3]));
            F2 w  = pk(wA, wB);
            F2 dg = fmul2(ffma2(C82, u[l], C7), FE[l]);
            F2 q  = fmul2(fmul2(w, dg), iv[l]);

            F2 da0  = fmul2(APH[l], chla);
            F2 dbb0 = fmul2(BBS[l], chla);
            F2 da2  = fmul2(ACD[l], cdom);
            F2 om   = ffma2(u[l], NEG1, ONE);

            F2 x0 = ffma2(fmul2(u[l], da0), NEG1, fmul2(om, dbb0));
            F2 x1 = ffma2(fmul2(u[l], da1), NEG1, fmul2(om, dbb1));
            F2 qun = fmul2(fmul2(q, u[l]), NEG1);
            if (l & 1) {
                h0 = ffma2(q, x0, h0);
                h1 = ffma2(q, x1, h1);
                h2 = ffma2(qun, da2, h2);
            } else {
                g0 = ffma2(q, x0, g0);
                g1 = ffma2(q, x1, g1);
                g2 = ffma2(qun, da2, g2);
            }
        }
        g0 = fadd2(g0, h0);
        g1 = fadd2(g1, h1);
        g2 = fadd2(g2, h2);

        // Adam with exact bias correction folded: mh/sqrt(vh) = m * rsqrt(v*E)
        b1t *= ADAM_B1;
        b2t *= ADAM_B2;
        float d1 = 1.0f - b1t;
        float Es = d1 * d1 * rcp_a(1.0f - b2t);
        F2 E2 = bc(Es);
        F2 g[3] = { g0, g1, g2 };
        #pragma unroll
        for (int k = 0; k < 3; k++) {
            m[k] = ffma2(g[k], C1MB1, fmul2(m[k], CB1));
            v[k] = ffma2(fmul2(g[k], g[k]), C1MB2, fmul2(v[k], CB2));
            F2 st = frsq2(ffma2(v[k], E2, TINY));
            ch[k] = ffma2(fmul2(m[k], st), NEGLR, ch[k]);
        }
    }

    // ---- outputs: [ch0, kd(5), bbp(3)] per pixel ----
    float kfac = p9 * 0.9f + p10 * 0.1f;
    float chL[3], chH[3];
    #pragma unroll
    for (int k = 0; k < 3; k++) upk(ch[k], chL[k], chH[k]);

    #pragma unroll
    for (int s = 0; s < 2; s++) {
        int b = s ? pB : pA;
        const float* chp = s ? chH : chL;
        float chla = __expf(chp[0]);
        float nap  = __expf(chp[1]);
        float cdom = __expf(chp[2]);

        out[b*9 + 0] = chp[0];
        #pragma unroll
        for (int l = 0; l < 5; l++) {
            float a  = 0.0045f + AphS[l]*chla + AcdS[l]*cdom + cna*nap;
            float bb = 0.0012f + BbsS[l]*chla + cnb*nap;
            float x3 = X[b*25 + l*5 + 3];
            float mu = 0.5f + 0.5f * rcp_a(1.0f + __expf(-x3));
            out[b*9 + 1 + l] = (a + bb) * rcp_a(mu) * kfac;
        }
        const float L3[3] = {0.025f, 0.5f, 1.15f};
        #pragma unroll
        for (int j = 0; j < 3; j++) {
            out[b*9 + 6 + j] = p11 * (p3 * 0.001f * chla * (1.0f + p4 * 0.05f * L3[j]) + cnb * nap);
        }
    }
}

extern "C" void kernel_launch(void* const* d_in, const int* in_sizes, int n_in,
                              void* d_out, int out_size) {
    const float* X    = (const float*)d_in[0];
    const float* Y    = (const float*)d_in[1];
    const float* ch0  = (const float*)d_in[2];
    const float* pf   = (const float*)d_in[3];
    const float* xa   = (const float*)d_in[4];
    const float* Sa   = (const float*)d_in[5];
    const float* Se   = (const float*)d_in[6];
    const int*   nit  = (n_in >= 8) ? (const int*)d_in[7] : nullptr;
    float* out = (float*)d_out;

    int B = in_sizes[1] / 5;   // Y is (B,5)
    int nThreads = (B + 1) / 2;

    const int TPB = 128;
    int blocks = (nThreads + TPB - 1) / TPB;
    pe_kernel<<<blocks, TPB>>>(X, Y, ch0, pf, xa, Sa, Se, nit, out, B);
}

// round 5
// speedup vs baseline: 1.5711x; 1.2721x over previous
#include <cuda_runtime.h>

#define ADAM_B1 0.9f
#define ADAM_B2 0.999f
#define ADAM_LR 0.02f

// ---------------- packed f32x2 helpers ----------------
struct F2 { unsigned long long v; };

__device__ __forceinline__ F2 pk(float lo, float hi) {
    F2 r; asm("mov.b64 %0, {%1, %2};" : "=l"(r.v) : "f"(lo), "f"(hi)); return r;
}
__device__ __forceinline__ void upk(F2 a, float& lo, float& hi) {
    asm("mov.b64 {%0, %1}, %2;" : "=f"(lo), "=f"(hi) : "l"(a.v));
}
__device__ __forceinline__ F2 bc(float s) { return pk(s, s); }
__device__ __forceinline__ F2 fadd2(F2 a, F2 b) {
    F2 r; asm("add.rn.f32x2 %0, %1, %2;" : "=l"(r.v) : "l"(a.v), "l"(b.v)); return r;
}
__device__ __forceinline__ F2 fmul2(F2 a, F2 b) {
    F2 r; asm("mul.rn.f32x2 %0, %1, %2;" : "=l"(r.v) : "l"(a.v), "l"(b.v)); return r;
}
__device__ __forceinline__ F2 ffma2(F2 a, F2 b, F2 c) {
    F2 r; asm("fma.rn.f32x2 %0, %1, %2, %3;" : "=l"(r.v) : "l"(a.v), "l"(b.v), "l"(c.v)); return r;
}

__device__ __forceinline__ float rcp_a(float x) {
    float r; asm("rcp.approx.f32 %0, %1;" : "=f"(r) : "f"(x)); return r;
}
__device__ __forceinline__ float rsq_a(float x) {
    float r; asm("rsqrt.approx.f32 %0, %1;" : "=f"(r) : "f"(x)); return r;
}
__device__ __forceinline__ float ex2_a(float x) {
    float r; asm("ex2.approx.f32 %0, %1;" : "=f"(r) : "f"(x)); return r;
}
__device__ __forceinline__ F2 frcp2(F2 a) {
    float lo, hi; upk(a, lo, hi); return pk(rcp_a(lo), rcp_a(hi));
}
__device__ __forceinline__ F2 frsq2(F2 a) {
    float lo, hi; upk(a, lo, hi); return pk(rsq_a(lo), rsq_a(hi));
}
__device__ __forceinline__ F2 fexp2(F2 a, F2 LOG2E) {
    F2 t = fmul2(a, LOG2E);
    float lo, hi; upk(t, lo, hi);
    return pk(ex2_a(lo), ex2_a(hi));
}

// ---------------- main kernel: 2 pixels per thread, packed ----------------
__global__ __launch_bounds__(128)
void pe_kernel(const float* __restrict__ X,     // (B,5,5)
               const float* __restrict__ Yg,    // (B,5)
               const float* __restrict__ ch0g,  // (B,1,3)
               const float* __restrict__ pf,    // (14,)
               const float* __restrict__ xag,   // (3,)
               const float* __restrict__ Sag,   // (3,3)
               const float* __restrict__ Seg,   // (5,5)
               const int*   __restrict__ nitp,
               float* __restrict__ out,         // (B,9)
               int B)
{
    int tIdx = blockIdx.x * blockDim.x + threadIdx.x;
    int pA = 2 * tIdx;
    if (pA >= B) return;
    int pB = min(pA + 1, B - 1);

    const float L[5] = {-0.275f, 0.025f, 0.5f, 0.70f, 1.15f};

    // ---- uniform (broadcast) parameters ----
    float p0=pf[0], p1=pf[1], p2=pf[2], p3=pf[3], p4=pf[4], p5=pf[5], p6=pf[6],
          p7=pf[7], p8=pf[8], p9=pf[9], p10=pf[10], p11=pf[11], p12=pf[12], p13=pf[13];

    float AphS[5], AcdS[5], BbsS[5];
    #pragma unroll
    for (int l = 0; l < 5; l++) {
        AphS[l] = p0 * 0.05f * (1.0f + p1 * 0.1f * L[l] + p2 * 0.01f);
        AcdS[l] = p5 * 0.1f * expf(-p6 * 1.7f * L[l]);
        BbsS[l] = p3 * 0.001f * (1.0f + p4 * 0.05f * L[l]);
    }
    const float cna = p12 * 0.005f;
    const float cnb = p13 * 0.005f;
    const float c7s = p7 * 0.089f;
    const float c8s = p8 * 0.1245f;

    // symmetrized matrices (scalar registers; uniform across warp)
    float Se[5][5];
    #pragma unroll
    for (int i = 0; i < 5; i++)
        #pragma unroll
        for (int j = 0; j < 5; j++)
            Se[i][j] = 0.5f * (Seg[i*5 + j] + Seg[j*5 + i]);
    float SaS[3][3];
    #pragma unroll
    for (int i = 0; i < 3; i++)
        #pragma unroll
        for (int j = 0; j < 3; j++)
            SaS[i][j] = 0.5f * (Sag[i*3 + j] + Sag[j*3 + i]);
    float xa0 = xag[0], xa1 = xag[1], xa2 = xag[2];

    // exact diagonality check (uniform branch)
    bool diag = (Se[0][1]==0.f && Se[0][2]==0.f && Se[0][3]==0.f && Se[0][4]==0.f &&
                 Se[1][2]==0.f && Se[1][3]==0.f && Se[1][4]==0.f &&
                 Se[2][3]==0.f && Se[2][4]==0.f && Se[3][4]==0.f &&
                 SaS[0][1]==0.f && SaS[0][2]==0.f && SaS[1][2]==0.f);

    // ---- packed per-wavelength constants (broadcast) ----
    const F2 APH[5] = { bc(AphS[0]), bc(AphS[1]), bc(AphS[2]), bc(AphS[3]), bc(AphS[4]) };
    const F2 ACD[5] = { bc(AcdS[0]), bc(AcdS[1]), bc(AcdS[2]), bc(AcdS[3]), bc(AcdS[4]) };
    const F2 BBS[5] = { bc(BbsS[0]), bc(BbsS[1]), bc(BbsS[2]), bc(BbsS[3]), bc(BbsS[4]) };
    const F2 CNA = bc(cna), CNB = bc(cnb);
    const F2 C7 = bc(c7s), C8 = bc(c8s), C82 = bc(2.0f * c8s);
    const F2 C0045 = bc(0.0045f), C0012 = bc(0.0012f);
    const F2 NEG1 = bc(-1.0f), ONE = bc(1.0f);
    const F2 LOG2E = bc(1.4426950408889634f);
    const F2 CB1 = bc(ADAM_B1), C1MB1 = bc(1.0f - ADAM_B1);
    const F2 CB2 = bc(ADAM_B2), C1MB2 = bc(1.0f - ADAM_B2);
    const F2 NEGLR = bc(-ADAM_LR), TINY = bc(1e-30f);

    // ---- per-pixel packed constants ----
    F2 FE[5], Yp[5];
    #pragma unroll
    for (int l = 0; l < 5; l++) {
        float eA0 = X[pA*25 + l*5 + 0], eA1 = X[pA*25 + l*5 + 1];
        float eB0 = X[pB*25 + l*5 + 0], eB1 = X[pB*25 + l*5 + 1];
        FE[l] = pk(__fdividef(eA0 + 0.5f*eA1, eA0 + eA1),
                   __fdividef(eB0 + 0.5f*eB1, eB0 + eB1));
        Yp[l] = pk(-Yg[pA*5 + l], -Yg[pB*5 + l]);   // negated: r = rrs + Yp
    }

    F2 ch[3], m[3], v[3];
    #pragma unroll
    for (int k = 0; k < 3; k++) {
        ch[k] = pk(ch0g[pA*3 + k], ch0g[pB*3 + k]);
        m[k] = bc(0.0f); v[k] = bc(0.0f);
    }

    // ---- iteration count ----
    int iters = 50;
    if (nitp) {
        int it = *nitp;
        if (it >= 1 && it <= 100000000) iters = it;
        else {
            float f = __int_as_float(it);
            if (f >= 1.0f && f <= 1e8f) iters = (int)f;
        }
    }

    float b1t = 1.0f, b2t = 1.0f;

    if (diag) {
        // =========== fused single-pass loop (diagonal Se, Sa) ===========
        const F2 SED[5] = { bc(Se[0][0]), bc(Se[1][1]), bc(Se[2][2]), bc(Se[3][3]), bc(Se[4][4]) };
        const F2 SAD[3] = { bc(SaS[0][0]), bc(SaS[1][1]), bc(SaS[2][2]) };
        const F2 BPD[3] = { bc(-SaS[0][0]*xa0), bc(-SaS[1][1]*xa1), bc(-SaS[2][2]*xa2) };

        for (int t = 0; t < iters; t++) {
            F2 chla = fexp2(ch[0], LOG2E);
            F2 nap  = fexp2(ch[1], LOG2E);
            F2 cdom = fexp2(ch[2], LOG2E);

            F2 da1   = fmul2(CNA, nap);
            F2 dbb1  = fmul2(CNB, nap);
            F2 dsum1 = fadd2(da1, dbb1);
            F2 DA1C  = fadd2(da1, C0045);
            F2 DB1C  = fadd2(dbb1, C0012);

            // prior gradient (diag)
            F2 g0 = ffma2(SAD[0], ch[0], BPD[0]);
            F2 g1 = ffma2(SAD[1], ch[1], BPD[1]);
            F2 g2 = ffma2(SAD[2], ch[2], BPD[2]);
            F2 h0 = bc(0.0f), h1 = bc(0.0f), h2 = bc(0.0f);

            #pragma unroll
            for (int l = 0; l < 5; l++) {
                F2 da0   = fmul2(APH[l], chla);
                F2 dbb0  = fmul2(BBS[l], chla);
                F2 da2   = fmul2(ACD[l], cdom);
                F2 dsum0 = fadd2(da0, dbb0);
                F2 a  = fadd2(fadd2(da0, da2), DA1C);
                F2 bb = fadd2(dbb0, DB1C);
                F2 iv = frcp2(fadd2(a, bb));
                F2 u  = fmul2(bb, iv);
                F2 t1 = ffma2(C8, u, C7);
                F2 rrs = fmul2(fmul2(t1, u), FE[l]);
                F2 r   = fadd2(rrs, Yp[l]);               // rrs - Y
                F2 dg  = fmul2(ffma2(C8, u, t1), FE[l]);  // (C7+2C8u)*FE
                F2 q   = fmul2(fmul2(fmul2(SED[l], r), dg), iv);
                F2 un  = fmul2(u, NEG1);
                F2 x0  = ffma2(un, dsum0, dbb0);
                F2 x1  = ffma2(un, dsum1, dbb1);
                F2 qu  = fmul2(q, un);                    // -q*u
                if (l & 1) {
                    h0 = ffma2(q, x0, h0);
                    h1 = ffma2(q, x1, h1);
                    h2 = ffma2(qu, da2, h2);
                } else {
                    g0 = ffma2(q, x0, g0);
                    g1 = ffma2(q, x1, g1);
                    g2 = ffma2(qu, da2, g2);
                }
            }
            g0 = fadd2(g0, h0); g1 = fadd2(g1, h1); g2 = fadd2(g2, h2);

            b1t *= ADAM_B1; b2t *= ADAM_B2;
            float d1 = 1.0f - b1t;
            F2 E2 = bc(d1 * d1 * rcp_a(1.0f - b2t));
            F2 g[3] = { g0, g1, g2 };
            #pragma unroll
            for (int k = 0; k < 3; k++) {
                m[k] = ffma2(g[k], C1MB1, fmul2(m[k], CB1));
                v[k] = ffma2(fmul2(g[k], g[k]), C1MB2, fmul2(v[k], CB2));
                F2 st = frsq2(ffma2(v[k], E2, TINY));
                ch[k] = ffma2(fmul2(m[k], st), NEGLR, ch[k]);
            }
        }
    } else {
        // =========== general two-pass loop (dense Se, Sa) ===========
        float bp0 = -(SaS[0][0]*xa0 + SaS[0][1]*xa1 + SaS[0][2]*xa2);
        float bp1 = -(SaS[1][0]*xa0 + SaS[1][1]*xa1 + SaS[1][2]*xa2);
        float bp2 = -(SaS[2][0]*xa0 + SaS[2][1]*xa1 + SaS[2][2]*xa2);

        for (int t = 0; t < iters; t++) {
            F2 chla = fexp2(ch[0], LOG2E);
            F2 nap  = fexp2(ch[1], LOG2E);
            F2 cdom = fexp2(ch[2], LOG2E);

            F2 da1  = fmul2(CNA, nap);
            F2 dbb1 = fmul2(CNB, nap);

            F2 u[5], iv[5];
            float rA[5], rB[5];
            #pragma unroll
            for (int l = 0; l < 5; l++) {
                F2 da0  = fmul2(APH[l], chla);
                F2 da2  = fmul2(ACD[l], cdom);
                F2 dbb0 = fmul2(BBS[l], chla);
                F2 a  = fadd2(fadd2(da0, da2), fadd2(da1, C0045));
                F2 bb = fadd2(dbb0, fadd2(dbb1, C0012));
                F2 ivv = frcp2(fadd2(a, bb));
                F2 uv  = fmul2(bb, ivv);
                F2 rrs = fmul2(fmul2(ffma2(C8, uv, C7), uv), FE[l]);
                F2 rr  = fadd2(rrs, Yp[l]);
                upk(rr, rA[l], rB[l]);
                u[l] = uv; iv[l] = ivv;
            }

            float cA0, cB0, cA1, cB1, cA2, cB2;
            upk(ch[0], cA0, cB0); upk(ch[1], cA1, cB1); upk(ch[2], cA2, cB2);
            float gA0 = fmaf(SaS[0][0], cA0, fmaf(SaS[0][1], cA1, fmaf(SaS[0][2], cA2, bp0)));
            float gB0 = fmaf(SaS[0][0], cB0, fmaf(SaS[0][1], cB1, fmaf(SaS[0][2], cB2, bp0)));
            float gA1 = fmaf(SaS[1][0], cA0, fmaf(SaS[1][1], cA1, fmaf(SaS[1][2], cA2, bp1)));
            float gB1 = fmaf(SaS[1][0], cB0, fmaf(SaS[1][1], cB1, fmaf(SaS[1][2], cB2, bp1)));
            float gA2 = fmaf(SaS[2][0], cA0, fmaf(SaS[2][1], cA1, fmaf(SaS[2][2], cA2, bp2)));
            float gB2 = fmaf(SaS[2][0], cB0, fmaf(SaS[2][1], cB1, fmaf(SaS[2][2], cB2, bp2)));
            F2 g0 = pk(gA0, gB0);
            F2 g1 = pk(gA1, gB1);
            F2 g2 = pk(gA2, gB2);

            #pragma unroll
            for (int l = 0; l < 5; l++) {
                float wA = fmaf(Se[l][4], rA[4],
                           fmaf(Se[l][0], rA[0], Se[l][1]*rA[1]) +
                           fmaf(Se[l][2], rA[2], Se[l][3]*rA[3]));
                float wB = fmaf(Se[l][4], rB[4],
                           fmaf(Se[l][0], rB[0], Se[l][1]*rB[1]) +
                           fmaf(Se[l][2], rB[2], Se[l][3]*rB[3]));
                F2 w  = pk(wA, wB);
                F2 dg = fmul2(ffma2(C82, u[l], C7), FE[l]);
                F2 q  = fmul2(fmul2(w, dg), iv[l]);

                F2 da0  = fmul2(APH[l], chla);
                F2 dbb0 = fmul2(BBS[l], chla);
                F2 da2  = fmul2(ACD[l], cdom);
                F2 om   = ffma2(u[l], NEG1, ONE);

                F2 x0 = ffma2(fmul2(u[l], da0), NEG1, fmul2(om, dbb0));
                F2 x1 = ffma2(fmul2(u[l], da1), NEG1, fmul2(om, dbb1));
                F2 qun = fmul2(fmul2(q, u[l]), NEG1);
                g0 = ffma2(q, x0, g0);
                g1 = ffma2(q, x1, g1);
                g2 = ffma2(qun, da2, g2);
            }

            b1t *= ADAM_B1; b2t *= ADAM_B2;
            float d1 = 1.0f - b1t;
            F2 E2 = bc(d1 * d1 * rcp_a(1.0f - b2t));
            F2 g[3] = { g0, g1, g2 };
            #pragma unroll
            for (int k = 0; k < 3; k++) {
                m[k] = ffma2(g[k], C1MB1, fmul2(m[k], CB1));
                v[k] = ffma2(fmul2(g[k], g[k]), C1MB2, fmul2(v[k], CB2));
                F2 st = frsq2(ffma2(v[k], E2, TINY));
                ch[k] = ffma2(fmul2(m[k], st), NEGLR, ch[k]);
            }
        }
    }

    // ---- outputs: [ch0, kd(5), bbp(3)] per pixel ----
    float kfac = p9 * 0.9f + p10 * 0.1f;
    float chL[3], chH[3];
    #pragma unroll
    for (int k = 0; k < 3; k++) upk(ch[k], chL[k], chH[k]);

    #pragma unroll
    for (int s = 0; s < 2; s++) {
        int b = s ? pB : pA;
        const float* chp = s ? chH : chL;
        float chla = __expf(chp[0]);
        float nap  = __expf(chp[1]);
        float cdom = __expf(chp[2]);

        out[b*9 + 0] = chp[0];
        #pragma unroll
        for (int l = 0; l < 5; l++) {
            float a  = 0.0045f + AphS[l]*chla + AcdS[l]*cdom + cna*nap;
            float bb = 0.0012f + BbsS[l]*chla + cnb*nap;
            float x3 = X[b*25 + l*5 + 3];
            float mu = 0.5f + 0.5f * rcp_a(1.0f + __expf(-x3));
            out[b*9 + 1 + l] = (a + bb) * rcp_a(mu) * kfac;
        }
        const float L3[3] = {0.025f, 0.5f, 1.15f};
        #pragma unroll
        for (int j = 0; j < 3; j++) {
            out[b*9 + 6 + j] = p11 * (p3 * 0.001f * chla * (1.0f + p4 * 0.05f * L3[j]) + cnb * nap);
        }
    }
}

extern "C" void kernel_launch(void* const* d_in, const int* in_sizes, int n_in,
                              void* d_out, int out_size) {
    const float* X    = (const float*)d_in[0];
    const float* Y    = (const float*)d_in[1];
    const float* ch0  = (const float*)d_in[2];
    const float* pf   = (const float*)d_in[3];
    const float* xa   = (const float*)d_in[4];
    const float* Sa   = (const float*)d_in[5];
    const float* Se   = (const float*)d_in[6];
    const int*   nit  = (n_in >= 8) ? (const int*)d_in[7] : nullptr;
    float* out = (float*)d_out;

    int B = in_sizes[1] / 5;   // Y is (B,5)
    int nThreads = (B + 1) / 2;

    const int TPB = 128;
    int blocks = (nThreads + TPB - 1) / TPB;
    pe_kernel<<<blocks, TPB>>>(X, Y, ch0, pf, xa, Sa, Se, nit, out, B);
}

// round 6
// speedup vs baseline: 1.7541x; 1.1164x over previous
#include <cuda_runtime.h>

#define ADAM_B1 0.9f
#define ADAM_B2 0.999f
#define ADAM_LR 0.02f

// ---------------- packed f32x2 helpers ----------------
struct F2 { unsigned long long v; };

__device__ __forceinline__ F2 pk(float lo, float hi) {
    F2 r; asm("mov.b64 %0, {%1, %2};" : "=l"(r.v) : "f"(lo), "f"(hi)); return r;
}
__device__ __forceinline__ void upk(F2 a, float& lo, float& hi) {
    asm("mov.b64 {%0, %1}, %2;" : "=f"(lo), "=f"(hi) : "l"(a.v));
}
__device__ __forceinline__ F2 bc(float s) { return pk(s, s); }
__device__ __forceinline__ F2 fadd2(F2 a, F2 b) {
    F2 r; asm("add.rn.f32x2 %0, %1, %2;" : "=l"(r.v) : "l"(a.v), "l"(b.v)); return r;
}
__device__ __forceinline__ F2 fmul2(F2 a, F2 b) {
    F2 r; asm("mul.rn.f32x2 %0, %1, %2;" : "=l"(r.v) : "l"(a.v), "l"(b.v)); return r;
}
__device__ __forceinline__ F2 ffma2(F2 a, F2 b, F2 c) {
    F2 r; asm("fma.rn.f32x2 %0, %1, %2, %3;" : "=l"(r.v) : "l"(a.v), "l"(b.v), "l"(c.v)); return r;
}

__device__ __forceinline__ float rcp_a(float x) {
    float r; asm("rcp.approx.f32 %0, %1;" : "=f"(r) : "f"(x)); return r;
}
__device__ __forceinline__ float rsq_a(float x) {
    float r; asm("rsqrt.approx.f32 %0, %1;" : "=f"(r) : "f"(x)); return r;
}
__device__ __forceinline__ float ex2_a(float x) {
    float r; asm("ex2.approx.f32 %0, %1;" : "=f"(r) : "f"(x)); return r;
}
__device__ __forceinline__ F2 frcp2(F2 a) {
    float lo, hi; upk(a, lo, hi); return pk(rcp_a(lo), rcp_a(hi));
}
__device__ __forceinline__ F2 frsq2(F2 a) {
    float lo, hi; upk(a, lo, hi); return pk(rsq_a(lo), rsq_a(hi));
}
__device__ __forceinline__ F2 fexp2(F2 a, F2 LOG2E) {
    F2 t = fmul2(a, LOG2E);
    float lo, hi; upk(t, lo, hi);
    return pk(ex2_a(lo), ex2_a(hi));
}

// ---------------- main kernel: 2 pixels per thread, packed ----------------
__global__ __launch_bounds__(32)
void pe_kernel(const float* __restrict__ X,     // (B,5,5)
               const float* __restrict__ Yg,    // (B,5)
               const float* __restrict__ ch0g,  // (B,1,3)
               const float* __restrict__ pf,    // (14,)
               const float* __restrict__ xag,   // (3,)
               const float* __restrict__ Sag,   // (3,3)
               const float* __restrict__ Seg,   // (5,5)
               const int*   __restrict__ nitp,
               float* __restrict__ out,         // (B,9)
               int B)
{
    int tIdx = blockIdx.x * blockDim.x + threadIdx.x;
    int pA = 2 * tIdx;
    if (pA >= B) return;
    int pB = min(pA + 1, B - 1);

    const float L[5] = {-0.275f, 0.025f, 0.5f, 0.70f, 1.15f};

    // ---- uniform (broadcast) parameters ----
    float p0=pf[0], p1=pf[1], p2=pf[2], p3=pf[3], p4=pf[4], p5=pf[5], p6=pf[6],
          p7=pf[7], p8=pf[8], p9=pf[9], p10=pf[10], p11=pf[11], p12=pf[12], p13=pf[13];

    float AphS[5], AcdS[5], BbsS[5];
    #pragma unroll
    for (int l = 0; l < 5; l++) {
        AphS[l] = p0 * 0.05f * (1.0f + p1 * 0.1f * L[l] + p2 * 0.01f);
        AcdS[l] = p5 * 0.1f * expf(-p6 * 1.7f * L[l]);
        BbsS[l] = p3 * 0.001f * (1.0f + p4 * 0.05f * L[l]);
    }
    const float cna = p12 * 0.005f;
    const float cnb = p13 * 0.005f;
    const float c7s = p7 * 0.089f;
    const float c8s = p8 * 0.1245f;

    // symmetrized matrices (uniform)
    float Se[5][5];
    #pragma unroll
    for (int i = 0; i < 5; i++)
        #pragma unroll
        for (int j = 0; j < 5; j++)
            Se[i][j] = 0.5f * (Seg[i*5 + j] + Seg[j*5 + i]);
    float SaS[3][3];
    #pragma unroll
    for (int i = 0; i < 3; i++)
        #pragma unroll
        for (int j = 0; j < 3; j++)
            SaS[i][j] = 0.5f * (Sag[i*3 + j] + Sag[j*3 + i]);
    float xa0 = xag[0], xa1 = xag[1], xa2 = xag[2];

    bool diag = (Se[0][1]==0.f && Se[0][2]==0.f && Se[0][3]==0.f && Se[0][4]==0.f &&
                 Se[1][2]==0.f && Se[1][3]==0.f && Se[1][4]==0.f &&
                 Se[2][3]==0.f && Se[2][4]==0.f && Se[3][4]==0.f &&
                 SaS[0][1]==0.f && SaS[0][2]==0.f && SaS[1][2]==0.f);

    // ---- common packed constants ----
    const F2 CNA = bc(cna), CNB = bc(cnb);
    const F2 C7 = bc(c7s), C8 = bc(c8s);
    const F2 C0012 = bc(0.0012f);
    const F2 NEG1 = bc(-1.0f);
    const F2 LOG2E = bc(1.4426950408889634f);
    const F2 CB1 = bc(ADAM_B1), C1MB1 = bc(1.0f - ADAM_B1);
    const F2 CB2 = bc(ADAM_B2), C1MB2 = bc(1.0f - ADAM_B2);
    const F2 NEGLR = bc(-ADAM_LR), TINY = bc(1e-30f);

    // ---- per-pixel setup ----
    float feA[5], feB[5];
    #pragma unroll
    for (int l = 0; l < 5; l++) {
        float eA0 = X[pA*25 + l*5 + 0], eA1 = X[pA*25 + l*5 + 1];
        float eB0 = X[pB*25 + l*5 + 0], eB1 = X[pB*25 + l*5 + 1];
        feA[l] = __fdividef(eA0 + 0.5f*eA1, eA0 + eA1);
        feB[l] = __fdividef(eB0 + 0.5f*eB1, eB0 + eB1);
    }

    F2 ch[3], m[3], v[3];
    #pragma unroll
    for (int k = 0; k < 3; k++) {
        ch[k] = pk(ch0g[pA*3 + k], ch0g[pB*3 + k]);
        m[k] = bc(0.0f); v[k] = bc(0.0f);
    }

    int iters = 50;
    if (nitp) {
        int it = *nitp;
        if (it >= 1 && it <= 100000000) iters = it;
        else {
            float f = __int_as_float(it);
            if (f >= 1.0f && f <= 1e8f) iters = (int)f;
        }
    }

    float b1t = 1.0f, b2t = 1.0f;

    if (diag) {
        // ===== fused diagonal path, factored gradients, tracked exps =====
        F2 ABSn[5], ACDn[5], BBSp[5], FE2[5], Yfn[5];
        #pragma unroll
        for (int l = 0; l < 5; l++) {
            ABSn[l] = bc(-(AphS[l] + BbsS[l]));
            ACDn[l] = bc(-AcdS[l]);
            BBSp[l] = bc(BbsS[l]);
            FE2[l]  = pk(Se[l][l]*feA[l]*feA[l], Se[l][l]*feB[l]*feB[l]);
            Yfn[l]  = pk(-__fdividef(Yg[pA*5 + l], feA[l]),
                         -__fdividef(Yg[pB*5 + l], feB[l]));
        }
        const F2 SAD[3] = { bc(SaS[0][0]), bc(SaS[1][1]), bc(SaS[2][2]) };
        const F2 BPD[3] = { bc(-SaS[0][0]*xa0), bc(-SaS[1][1]*xa1), bc(-SaS[2][2]*xa2) };
        const F2 C0057 = bc(0.0057f);
        const F2 ONE = bc(1.0f), CHALF = bc(0.5f);
        const F2 C6I = bc(1.0f/6.0f), C24I = bc(1.0f/24.0f);

        // tracked exponentials (refreshed exactly once at start)
        F2 ex0 = fexp2(ch[0], LOG2E);   // chla
        F2 ex1 = fexp2(ch[1], LOG2E);   // nap
        F2 ex2v = fexp2(ch[2], LOG2E);  // cdom

        for (int t = 0; t < iters; t++) {
            F2 chla = ex0, nap = ex1, cdom = ex2v;

            F2 da1   = fmul2(CNA, nap);
            F2 dbb1  = fmul2(CNB, nap);
            F2 dsum1 = fadd2(da1, dbb1);
            F2 NC    = fadd2(dsum1, C0057);
            F2 DB1C  = fadd2(dbb1, C0012);
            F2 chlan = fmul2(chla, NEG1);
            F2 cdomn = fmul2(cdom, NEG1);

            F2 acc0 = bc(0.0f), S0 = bc(0.0f), S1 = bc(0.0f), acc2 = bc(0.0f);

            #pragma unroll
            for (int l = 0; l < 5; l++) {
                F2 m0   = fmul2(ABSn[l], chlan);          // (Aph+Bbs)*chla
                F2 s    = ffma2(ACDn[l], cdomn, fadd2(m0, NC)); // a+bb
                F2 dbb0 = fmul2(BBSp[l], chla);
                F2 bb   = fadd2(dbb0, DB1C);
                F2 iv   = frcp2(s);
                F2 u    = fmul2(bb, iv);
                F2 t1   = ffma2(C8, u, C7);
                F2 p    = ffma2(t1, u, Yfn[l]);           // t1*u - Y/FE
                F2 d    = ffma2(C8, u, t1);               // c7 + 2 c8 u
                F2 q    = fmul2(fmul2(FE2[l], iv), fmul2(p, d));
                F2 qu   = fmul2(q, u);
                F2 tg   = ffma2(u, ABSn[l], BBSp[l]);     // BBS - u*(Aph+Bbs)
                acc0 = ffma2(q, tg, acc0);
                S0   = fadd2(S0, q);
                S1   = fadd2(S1, qu);
                acc2 = ffma2(qu, ACDn[l], acc2);          // -sum qu*ACD
            }

            // assemble gradients
            F2 g0 = ffma2(acc0, chla, ffma2(SAD[0], ch[0], BPD[0]));
            F2 dsum1n = fmul2(dsum1, NEG1);
            F2 g1 = ffma2(SAD[1], ch[1], BPD[1]);
            g1 = ffma2(dbb1, S0, g1);
            g1 = ffma2(dsum1n, S1, g1);
            F2 g2 = ffma2(acc2, cdom, ffma2(SAD[2], ch[2], BPD[2]));

            b1t *= ADAM_B1; b2t *= ADAM_B2;
            float d1s = 1.0f - b1t;
            F2 E2 = bc(d1s * d1s * rcp_a(1.0f - b2t));

            F2 g[3] = { g0, g1, g2 };
            F2* exs[3] = { &ex0, &ex1, &ex2v };
            #pragma unroll
            for (int k = 0; k < 3; k++) {
                m[k] = ffma2(g[k], C1MB1, fmul2(m[k], CB1));
                v[k] = ffma2(fmul2(g[k], g[k]), C1MB2, fmul2(v[k], CB2));
                F2 st  = frsq2(ffma2(v[k], E2, TINY));
                F2 dlt = fmul2(fmul2(m[k], st), NEGLR);
                ch[k] = fadd2(ch[k], dlt);
                // e^dlt via degree-4 poly (|dlt| <= ~0.07)
                F2 h = ffma2(dlt, C24I, C6I);
                h = ffma2(dlt, h, CHALF);
                h = ffma2(dlt, h, ONE);
                h = ffma2(dlt, h, ONE);
                *exs[k] = fmul2(*exs[k], h);
            }
        }
    } else {
        // ===== general two-pass fallback (dense Se, Sa) =====
        const F2 C0045 = bc(0.0045f), ONEg = bc(1.0f);
        const F2 C82 = bc(2.0f * c8s);
        const F2 APH[5] = { bc(AphS[0]), bc(AphS[1]), bc(AphS[2]), bc(AphS[3]), bc(AphS[4]) };
        const F2 ACD[5] = { bc(AcdS[0]), bc(AcdS[1]), bc(AcdS[2]), bc(AcdS[3]), bc(AcdS[4]) };
        const F2 BBS[5] = { bc(BbsS[0]), bc(BbsS[1]), bc(BbsS[2]), bc(BbsS[3]), bc(BbsS[4]) };
        F2 FE[5], Yp[5];
        #pragma unroll
        for (int l = 0; l < 5; l++) {
            FE[l] = pk(feA[l], feB[l]);
            Yp[l] = pk(-Yg[pA*5 + l], -Yg[pB*5 + l]);
        }
        float bp0 = -(SaS[0][0]*xa0 + SaS[0][1]*xa1 + SaS[0][2]*xa2);
        float bp1 = -(SaS[1][0]*xa0 + SaS[1][1]*xa1 + SaS[1][2]*xa2);
        float bp2 = -(SaS[2][0]*xa0 + SaS[2][1]*xa1 + SaS[2][2]*xa2);

        for (int t = 0; t < iters; t++) {
            F2 chla = fexp2(ch[0], LOG2E);
            F2 nap  = fexp2(ch[1], LOG2E);
            F2 cdom = fexp2(ch[2], LOG2E);

            F2 da1  = fmul2(CNA, nap);
            F2 dbb1 = fmul2(CNB, nap);

            F2 u[5], iv[5];
            float rA[5], rB[5];
            #pragma unroll
            for (int l = 0; l < 5; l++) {
                F2 da0  = fmul2(APH[l], chla);
                F2 da2  = fmul2(ACD[l], cdom);
                F2 dbb0 = fmul2(BBS[l], chla);
                F2 a  = fadd2(fadd2(da0, da2), fadd2(da1, C0045));
                F2 bb = fadd2(dbb0, fadd2(dbb1, C0012));
                F2 ivv = frcp2(fadd2(a, bb));
                F2 uv  = fmul2(bb, ivv);
                F2 rrs = fmul2(fmul2(ffma2(C8, uv, C7), uv), FE[l]);
                F2 rr  = fadd2(rrs, Yp[l]);
                upk(rr, rA[l], rB[l]);
                u[l] = uv; iv[l] = ivv;
            }

            float cA0, cB0, cA1, cB1, cA2, cB2;
            upk(ch[0], cA0, cB0); upk(ch[1], cA1, cB1); upk(ch[2], cA2, cB2);
            float gA0 = fmaf(SaS[0][0], cA0, fmaf(SaS[0][1], cA1, fmaf(SaS[0][2], cA2, bp0)));
            float gB0 = fmaf(SaS[0][0], cB0, fmaf(SaS[0][1], cB1, fmaf(SaS[0][2], cB2, bp0)));
            float gA1 = fmaf(SaS[1][0], cA0, fmaf(SaS[1][1], cA1, fmaf(SaS[1][2], cA2, bp1)));
            float gB1 = fmaf(SaS[1][0], cB0, fmaf(SaS[1][1], cB1, fmaf(SaS[1][2], cB2, bp1)));
            float gA2 = fmaf(SaS[2][0], cA0, fmaf(SaS[2][1], cA1, fmaf(SaS[2][2], cA2, bp2)));
            float gB2 = fmaf(SaS[2][0], cB0, fmaf(SaS[2][1], cB1, fmaf(SaS[2][2], cB2, bp2)));
            F2 g0 = pk(gA0, gB0);
            F2 g1 = pk(gA1, gB1);
            F2 g2 = pk(gA2, gB2);

            #pragma unroll
            for (int l = 0; l < 5; l++) {
                float wA = fmaf(Se[l][4], rA[4],
                           fmaf(Se[l][0], rA[0], Se[l][1]*rA[1]) +
                           fmaf(Se[l][2], rA[2], Se[l][3]*rA[3]));
                float wB = fmaf(Se[l][4], rB[4],
                           fmaf(Se[l][0], rB[0], Se[l][1]*rB[1]) +
                           fmaf(Se[l][2], rB[2], Se[l][3]*rB[3]));
                F2 w  = pk(wA, wB);
                F2 dg = fmul2(ffma2(C82, u[l], C7), FE[l]);
                F2 q  = fmul2(fmul2(w, dg), iv[l]);

                F2 da0  = fmul2(APH[l], chla);
                F2 dbb0 = fmul2(BBS[l], chla);
                F2 da2  = fmul2(ACD[l], cdom);
                F2 om   = ffma2(u[l], NEG1, ONEg);

                F2 x0 = ffma2(fmul2(u[l], da0), NEG1, fmul2(om, dbb0));
                F2 x1 = ffma2(fmul2(u[l], da1), NEG1, fmul2(om, dbb1));
                F2 qun = fmul2(fmul2(q, u[l]), NEG1);
                g0 = ffma2(q, x0, g0);
                g1 = ffma2(q, x1, g1);
                g2 = ffma2(qun, da2, g2);
            }

            b1t *= ADAM_B1; b2t *= ADAM_B2;
            float d1s = 1.0f - b1t;
            F2 E2 = bc(d1s * d1s * rcp_a(1.0f - b2t));
            F2 g[3] = { g0, g1, g2 };
            #pragma unroll
            for (int k = 0; k < 3; k++) {
                m[k] = ffma2(g[k], C1MB1, fmul2(m[k], CB1));
                v[k] = ffma2(fmul2(g[k], g[k]), C1MB2, fmul2(v[k], CB2));
                F2 st = frsq2(ffma2(v[k], E2, TINY));
                ch[k] = ffma2(fmul2(m[k], st), NEGLR, ch[k]);
            }
        }
    }

    // ---- outputs: [ch0, kd(5), bbp(3)] per pixel ----
    float kfac = p9 * 0.9f + p10 * 0.1f;
    float chL[3], chH[3];
    #pragma unroll
    for (int k = 0; k < 3; k++) upk(ch[k], chL[k], chH[k]);

    #pragma unroll
    for (int s = 0; s < 2; s++) {
        int b = s ? pB : pA;
        const float* chp = s ? chH : chL;
        float chla = __expf(chp[0]);
        float nap  = __expf(chp[1]);
        float cdom = __expf(chp[2]);

        out[b*9 + 0] = chp[0];
        #pragma unroll
        for (int l = 0; l < 5; l++) {
            float a  = 0.0045f + AphS[l]*chla + AcdS[l]*cdom + cna*nap;
            float bb = 0.0012f + BbsS[l]*chla + cnb*nap;
            float x3 = X[b*25 + l*5 + 3];
            float mu = 0.5f + 0.5f * rcp_a(1.0f + __expf(-x3));
            out[b*9 + 1 + l] = (a + bb) * rcp_a(mu) * kfac;
        }
        const float L3[3] = {0.025f, 0.5f, 1.15f};
        #pragma unroll
        for (int j = 0; j < 3; j++) {
            out[b*9 + 6 + j] = p11 * (p3 * 0.001f * chla * (1.0f + p4 * 0.05f * L3[j]) + cnb * nap);
        }
    }
}

extern "C" void kernel_launch(void* const* d_in, const int* in_sizes, int n_in,
                              void* d_out, int out_size) {
    const float* X    = (const float*)d_in[0];
    const float* Y    = (const float*)d_in[1];
    const float* ch0  = (const float*)d_in[2];
    const float* pf   = (const float*)d_in[3];
    const float* xa   = (const float*)d_in[4];
    const float* Sa   = (const float*)d_in[5];
    const float* Se   = (const float*)d_in[6];
    const int*   nit  = (n_in >= 8) ? (const int*)d_in[7] : nullptr;
    float* out = (float*)d_out;

    int B = in_sizes[1] / 5;   // Y is (B,5)
    int nThreads = (B + 1) / 2;

    const int TPB = 32;   // fine-grained blocks: 11-vs-10 warps/SM balance
    int blocks = (nThreads + TPB - 1) / TPB;
    pe_kernel<<<blocks, TPB>>>(X, Y, ch0, pf, xa, Sa, Se, nit, out, B);
}